// round 15
// baseline (speedup 1.0000x reference)
#include <cuda_runtime.h>
#include <cuda_fp16.h>
#include <math.h>
#include <stdint.h>

#define B 2
#define NN 2048
#define C 512
#define H 8
#define D 64
#define SCALE_LOG2E 0.06376435597741051f      // 512^-0.5 * log2(e)

// -------- fp16 pre-converted inputs -----------------------------------------
__device__ __half g_q16 [B * NN * C];
__device__ __half g_kv16[B * NN * C];
__device__ __half g_Wth[4 * C * C], g_Wtl[4 * C * C];    // W^T [n][k] hi/lo
// -------- attention operands -------------------------------------------------
__device__ __half g_Q [B * H * NN * D];                  // Q fp16, scale*log2e folded
__device__ __half g_K [B * H * NN * D];                  // K fp16
__device__ __half g_VT[B * H * D * NN];                  // [bh][d][n]
__device__ __half g_AO16[B * NN * C];                    // attention out, fp16

// ---------------------------------------------------------------------------
#define MMAF16(c, a0, a1, a2, a3, b0, b1)                                     \
    asm volatile("mma.sync.aligned.m16n8k16.row.col.f32.f16.f16.f32 "         \
        "{%0,%1,%2,%3}, {%4,%5,%6,%7}, {%8,%9}, {%0,%1,%2,%3};"               \
        : "+f"((c)[0]), "+f"((c)[1]), "+f"((c)[2]), "+f"((c)[3])              \
        : "r"(a0), "r"(a1), "r"(a2), "r"(a3), "r"(b0), "r"(b1))

#define MMAF16H(d0, d1, a0, a1, a2, a3, b0, b1)                               \
    asm volatile("mma.sync.aligned.m16n8k16.row.col.f16.f16.f16.f16 "         \
        "{%0,%1}, {%2,%3,%4,%5}, {%6,%7}, {%0,%1};"                           \
        : "+r"(d0), "+r"(d1)                                                  \
        : "r"(a0), "r"(a1), "r"(a2), "r"(a3), "r"(b0), "r"(b1))

#define CP16(dst, src) asm volatile(                                          \
    "cp.async.cg.shared.global [%0], [%1], 16;" :: "r"(dst), "l"(src))
#define CP_COMMIT() asm volatile("cp.async.commit_group;" ::: "memory")
#define CP_WAIT0()  asm volatile("cp.async.wait_group 0;" ::: "memory")
#define CP_WAIT1()  asm volatile("cp.async.wait_group 1;" ::: "memory")

__device__ __forceinline__ void ldmatrix_x4(uint32_t& r0, uint32_t& r1,
                                            uint32_t& r2, uint32_t& r3, uint32_t addr) {
    asm volatile("ldmatrix.sync.aligned.m8n8.x4.shared.b16 {%0,%1,%2,%3}, [%4];"
        : "=r"(r0), "=r"(r1), "=r"(r2), "=r"(r3) : "r"(addr));
}
__device__ __forceinline__ uint32_t ex2_h2(uint32_t x) {
    uint32_t r;
    asm("ex2.approx.f16x2 %0, %1;" : "=r"(r) : "r"(x));
    return r;
}
__device__ __forceinline__ uint32_t smem_u32(const void* p) {
    uint32_t a;
    asm("{ .reg .u64 t; cvta.to.shared.u64 t, %1; cvt.u32.u64 %0, t; }" : "=r"(a) : "l"(p));
    return a;
}
__device__ __forceinline__ uint32_t h2bits(__half2 h) {
    return *reinterpret_cast<uint32_t*>(&h);
}
__device__ __forceinline__ uint32_t pack_h2(float a, float b) {
    return h2bits(__floats2half2_rn(a, b));
}
__device__ __forceinline__ void split_pack(float a, float b, uint32_t& hi, uint32_t& lo) {
    __half2 h = __floats2half2_rn(a, b);
    hi = h2bits(h);
    float2 f = __half22float2(h);
    lo = pack_h2(a - f.x, b - f.y);
}

// ---------------------------------------------------------------------------
// Fused pre-pass: z=0,1 -> q/kv fp32->fp16; z=2..5 -> W transpose+split
// ---------------------------------------------------------------------------
__global__ __launch_bounds__(256) void convert_all(
    const float* __restrict__ q, const float* __restrict__ kv,
    const float* __restrict__ Wq, const float* __restrict__ Wk,
    const float* __restrict__ Wv, const float* __restrict__ Wo)
{
    const int z = blockIdx.z;
    if (z < 2) {
        const float* src = z ? kv : q;
        __half* dst = z ? g_kv16 : g_q16;
        const size_t i4 = ((size_t)blockIdx.y * 128 + blockIdx.x) * 256 + threadIdx.x;
        float4 v = ((const float4*)src)[i4];
        ((uint2*)dst)[i4] = make_uint2(pack_h2(v.x, v.y), pack_h2(v.z, v.w));
        return;
    }
    if (blockIdx.x >= 16) return;
    const int mat = z - 2;
    const float* W = (mat == 0) ? Wq : (mat == 1) ? Wk : (mat == 2) ? Wv : Wo;
    __half* outh = g_Wth + (size_t)mat * C * C;
    __half* outl = g_Wtl + (size_t)mat * C * C;

    __shared__ float tile[32][33];
    const int k0 = blockIdx.y * 32;
    const int n0 = blockIdx.x * 32;
    const int tx = threadIdx.x & 31;
    const int ty = threadIdx.x >> 5;

    #pragma unroll
    for (int i = 0; i < 4; i++) {
        const int r = ty + i * 8;
        tile[r][tx] = W[(size_t)(k0 + r) * C + n0 + tx];
    }
    __syncthreads();

    const int n = threadIdx.x >> 3;
    const int p = threadIdx.x & 7;
    #pragma unroll
    for (int i = 0; i < 2; i++) {
        const int pp = p + i * 8;
        float f0 = tile[2 * pp][n];
        float f1 = tile[2 * pp + 1][n];
        uint32_t hi, lo;
        split_pack(f0, f1, hi, lo);
        *(uint32_t*)&outh[(size_t)(n0 + n) * C + k0 + 2 * pp] = hi;
        *(uint32_t*)&outl[(size_t)(n0 + n) * C + k0 + 2 * pp] = lo;
    }
}

// ---------------------------------------------------------------------------
// fp16 GEMM body (256 threads, warp tile 32x64), BK=64, 2-product split.
// Row stride 144B. Stage: sA@0, sWh@18432, sWl@36864; stride 55296; 2 stages.
// ---------------------------------------------------------------------------
#define RS 144

__device__ __forceinline__ void gemm_body_f16(
    const __half* __restrict__ A,
    const __half* __restrict__ Wth, const __half* __restrict__ Wtl,
    int row0, int col0, float acc[2][8][4], char* dsm)
{
    const uint32_t sb = smem_u32(dsm);
    const int t    = threadIdx.x;
    const int lane = t & 31;
    const int gid  = lane >> 2;
    const int tq   = lane & 3;
    const int wm   = (t >> 5) >> 1;
    const int wn   = (t >> 5) & 1;

    #define ISSUE_STAGE(st, k0)                                                       \
    do {                                                                              \
        const uint32_t bb_ = sb + (uint32_t)(st) * 55296u;                            \
        _Pragma("unroll")                                                             \
        for (int c_ = 0; c_ < 4; c_++) {                                              \
            const int ch_ = t + c_ * 256;                                             \
            const int r_ = ch_ >> 3, q_ = ch_ & 7;                                    \
            const uint32_t d_ = (uint32_t)(r_ * RS + q_ * 16);                        \
            CP16(bb_ + d_,           A   + (size_t)(row0 + r_) * C + (k0) + q_ * 8);  \
            CP16(bb_ + 18432u + d_,  Wth + (size_t)(col0 + r_) * C + (k0) + q_ * 8);  \
            CP16(bb_ + 36864u + d_,  Wtl + (size_t)(col0 + r_) * C + (k0) + q_ * 8);  \
        }                                                                             \
        CP_COMMIT();                                                                  \
    } while (0)

    ISSUE_STAGE(0, 0);

    for (int it = 0; it < 8; it++) {
        CP_WAIT0();
        __syncthreads();
        if (it < 7) ISSUE_STAGE((it + 1) & 1, (it + 1) * 64);

        const char* stg = dsm + (it & 1) * 55296;
        #pragma unroll
        for (int kk = 0; kk < 4; kk++) {
            const int kb = (kk * 8 + tq) * 4;
            uint32_t Af[2][4];
            #pragma unroll
            for (int mf = 0; mf < 2; mf++) {
                const int m0 = wm * 32 + mf * 16;
                const uint32_t oa = (uint32_t)((m0 + gid) * RS + kb);
                const uint32_t ob = (uint32_t)((m0 + gid + 8) * RS + kb);
                Af[mf][0] = *(const uint32_t*)(stg + oa);
                Af[mf][1] = *(const uint32_t*)(stg + ob);
                Af[mf][2] = *(const uint32_t*)(stg + oa + 16);
                Af[mf][3] = *(const uint32_t*)(stg + ob + 16);
            }
            #pragma unroll
            for (int nf = 0; nf < 8; nf++) {
                const int n = wn * 64 + nf * 8 + gid;
                const uint32_t ow = (uint32_t)(n * RS + kb);
                uint32_t bh0 = *(const uint32_t*)(stg + 18432 + ow);
                uint32_t bh1 = *(const uint32_t*)(stg + 18432 + ow + 16);
                uint32_t bl0 = *(const uint32_t*)(stg + 36864 + ow);
                uint32_t bl1 = *(const uint32_t*)(stg + 36864 + ow + 16);
                #pragma unroll
                for (int mf = 0; mf < 2; mf++) {
                    MMAF16(acc[mf][nf], Af[mf][0], Af[mf][1], Af[mf][2], Af[mf][3], bh0, bh1);
                    MMAF16(acc[mf][nf], Af[mf][0], Af[mf][1], Af[mf][2], Af[mf][3], bl0, bl1);
                }
            }
        }
        __syncthreads();
    }
    #undef ISSUE_STAGE
}

#define GEMM_SMEM 110592

// ---------------------------------------------------------------------------
// QKV projection (M128 tiles, 256 threads): z = 0:Q, 1:K, 2:V
// ---------------------------------------------------------------------------
__global__ __launch_bounds__(256, 2) void proj_mma_kernel(
    const float* __restrict__ pos_q, const float* __restrict__ pos_k)
{
    extern __shared__ char dsm[];
    const int which = blockIdx.z;
    const __half* A   = (which == 0) ? g_q16 : g_kv16;
    const __half* Wth = g_Wth + (size_t)which * C * C;
    const __half* Wtl = g_Wtl + (size_t)which * C * C;

    const int row0 = blockIdx.y * 128;
    const int col0 = blockIdx.x * 128;

    float acc[2][8][4];
    #pragma unroll
    for (int mf = 0; mf < 2; mf++)
        #pragma unroll
        for (int nf = 0; nf < 8; nf++)
            #pragma unroll
            for (int i = 0; i < 4; i++) acc[mf][nf][i] = 0.f;

    gemm_body_f16(A, Wth, Wtl, row0, col0, acc, dsm);

    const int lane = threadIdx.x & 31;
    const int gid = lane >> 2, tq = lane & 3;
    const int wm = (threadIdx.x >> 5) >> 1, wn = (threadIdx.x >> 5) & 1;

    #pragma unroll
    for (int mf = 0; mf < 2; mf++) {
        const int rA = row0 + wm * 32 + mf * 16 + gid;
        const int rB = rA + 8;
        const int bb = rA >> 11;
        const int nA = rA & (NN - 1);
        const int nB = rB & (NN - 1);
        #pragma unroll
        for (int nf = 0; nf < 8; nf++) {
            const int cc = col0 + wn * 64 + nf * 8 + tq * 2;
            const int hd = cc >> 6;
            const int dd = cc & 63;
            float v0 = acc[mf][nf][0], v1 = acc[mf][nf][1];
            float v2 = acc[mf][nf][2], v3 = acc[mf][nf][3];

            if (which == 0) {
                float2 pA = *(const float2*)&pos_q[((size_t)bb * NN + nA) * D + dd];
                float2 pB = *(const float2*)&pos_q[((size_t)bb * NN + nB) * D + dd];
                v0 = (v0 + pA.x) * SCALE_LOG2E; v1 = (v1 + pA.y) * SCALE_LOG2E;
                v2 = (v2 + pB.x) * SCALE_LOG2E; v3 = (v3 + pB.y) * SCALE_LOG2E;
                const size_t dA = (((size_t)bb * H + hd) * NN + nA) * D + dd;
                const size_t dB = (((size_t)bb * H + hd) * NN + nB) * D + dd;
                *(uint32_t*)&g_Q[dA] = pack_h2(v0, v1);
                *(uint32_t*)&g_Q[dB] = pack_h2(v2, v3);
            } else if (which == 1) {
                float2 pA = *(const float2*)&pos_k[((size_t)bb * NN + nA) * D + dd];
                float2 pB = *(const float2*)&pos_k[((size_t)bb * NN + nB) * D + dd];
                v0 += pA.x; v1 += pA.y; v2 += pB.x; v3 += pB.y;
                const size_t dA = (((size_t)bb * H + hd) * NN + nA) * D + dd;
                const size_t dB = (((size_t)bb * H + hd) * NN + nB) * D + dd;
                *(uint32_t*)&g_K[dA] = pack_h2(v0, v1);
                *(uint32_t*)&g_K[dB] = pack_h2(v2, v3);
            } else {
                const size_t base = ((size_t)bb * H + hd) * D;
                g_VT[(base + dd)     * NN + nA] = __float2half(v0);
                g_VT[(base + dd + 1) * NN + nA] = __float2half(v1);
                g_VT[(base + dd)     * NN + nB] = __float2half(v2);
                g_VT[(base + dd + 1) * NN + nB] = __float2half(v3);
            }
        }
    }
}

// ---------------------------------------------------------------------------
// FA2 flash attention: 512 threads, q-tile 256, key tile 64, 3-stage pipeline.
// ---------------------------------------------------------------------------
#define TK 64
#define TSWZ(r, cb) ((r) * 128 + ((cb) ^ (((r) & 7) << 4)))
#define ATTN_SMEM 49152

__global__ __launch_bounds__(512, 1) void attn_kernel()
{
    extern __shared__ char dsm[];
    const uint32_t sb = smem_u32(dsm);

    const int t    = threadIdx.x;
    const int w    = t >> 5;
    const int lane = t & 31;
    const int gid  = lane >> 2;
    const int tq   = lane & 3;
    const int bh   = blockIdx.y;
    const int q0   = blockIdx.x * 256;

    const int rch = t >> 3;
    const int cch = t & 7;

    const int lg = lane >> 3;
    const int lr = lane & 7;
    const int lx = lr << 4;
    const uint32_t kSel = (uint32_t)((lg & 1) << 4);
    const uint32_t rowOff = (uint32_t)((((lg >> 1) << 3) + lr) * 128);

    #define ISSUE_TILE(st, j0)                                                        \
    do {                                                                              \
        const uint32_t bb_ = sb + (uint32_t)(st) * 16384u;                            \
        const uint32_t d_ = TSWZ(rch, cch * 16);                                      \
        CP16(bb_ + d_,          g_K  + ((size_t)bh * NN + (j0) + rch) * D + cch * 8); \
        CP16(bb_ + 8192u + d_,  g_VT + ((size_t)bh * D + rch) * NN + (j0) + cch * 8); \
        CP_COMMIT();                                                                  \
    } while (0)

    uint32_t Ah[4][4];
    {
        const int r0 = q0 + w * 16 + gid;
        const __half* qh0 = g_Q + ((size_t)bh * NN + r0) * D;
        const __half* qh1 = qh0 + 8 * D;
        #pragma unroll
        for (int ks = 0; ks < 4; ks++) {
            const int k = ks * 16 + tq * 2;
            Ah[ks][0] = *(const uint32_t*)(qh0 + k);
            Ah[ks][1] = *(const uint32_t*)(qh1 + k);
            Ah[ks][2] = *(const uint32_t*)(qh0 + k + 8);
            Ah[ks][3] = *(const uint32_t*)(qh1 + k + 8);
        }
    }

    float O[8][4];
    #pragma unroll
    for (int nf = 0; nf < 8; nf++)
        #pragma unroll
        for (int i = 0; i < 4; i++) O[nf][i] = 0.f;
    float l0 = 0.f, l1 = 0.f;

    ISSUE_TILE(0, 0);
    ISSUE_TILE(1, TK);

    int stc = 0;
    for (int jt = 0; jt < NN / TK; jt++) {
        CP_WAIT1();
        __syncthreads();
        if (jt + 2 < NN / TK) {
            int sti = stc + 2; if (sti >= 3) sti -= 3;
            ISSUE_TILE(sti, (jt + 2) * TK);
        }

        const uint32_t stg = sb + (uint32_t)stc * 16384u;

        uint32_t sh[8][2];
        #pragma unroll
        for (int nf = 0; nf < 8; nf++) { sh[nf][0] = 0u; sh[nf][1] = 0u; }

        #pragma unroll
        for (int ks = 0; ks < 4; ks++) {
            const uint32_t kcb = ((uint32_t)(ks * 32) + kSel) ^ (uint32_t)lx;
            #pragma unroll
            for (int np = 0; np < 4; np++) {
                const uint32_t addr = stg + (uint32_t)(np * 2048) + rowOff + kcb;
                uint32_t b0, b1, b2, b3;
                ldmatrix_x4(b0, b1, b2, b3, addr);
                MMAF16H(sh[2 * np][0],     sh[2 * np][1],
                        Ah[ks][0], Ah[ks][1], Ah[ks][2], Ah[ks][3], b0, b1);
                MMAF16H(sh[2 * np + 1][0], sh[2 * np + 1][1],
                        Ah[ks][0], Ah[ks][1], Ah[ks][2], Ah[ks][3], b2, b3);
            }
        }

        uint32_t ph[8][2];
        __half2 la0 = __floats2half2_rn(0.f, 0.f);
        __half2 la1 = la0;
        #pragma unroll
        for (int nf = 0; nf < 8; nf++) {
            ph[nf][0] = ex2_h2(sh[nf][0]);
            ph[nf][1] = ex2_h2(sh[nf][1]);
            la0 = __hadd2(la0, *(__half2*)&ph[nf][0]);
            la1 = __hadd2(la1, *(__half2*)&ph[nf][1]);
        }
        {
            float2 f0 = __half22float2(la0);
            float2 f1 = __half22float2(la1);
            l0 += f0.x + f0.y;
            l1 += f1.x + f1.y;
        }

        #pragma unroll
        for (int ks = 0; ks < 4; ks++) {
            const uint32_t a0 = ph[2 * ks][0],     a1 = ph[2 * ks][1];
            const uint32_t a2 = ph[2 * ks + 1][0], a3 = ph[2 * ks + 1][1];
            const uint32_t kcb = ((uint32_t)(ks * 32) + kSel) ^ (uint32_t)lx;
            #pragma unroll
            for (int np = 0; np < 4; np++) {
                const uint32_t addr = stg + 8192u + (uint32_t)(np * 2048) + rowOff + kcb;
                uint32_t bv0, bv1, bv2, bv3;
                ldmatrix_x4(bv0, bv1, bv2, bv3, addr);
                MMAF16(O[2 * np],     a0, a1, a2, a3, bv0, bv1);
                MMAF16(O[2 * np + 1], a0, a1, a2, a3, bv2, bv3);
            }
        }
        __syncthreads();
        if (++stc == 3) stc = 0;
    }
    #undef ISSUE_TILE

    l0 += __shfl_xor_sync(0xffffffffu, l0, 1);
    l0 += __shfl_xor_sync(0xffffffffu, l0, 2);
    l1 += __shfl_xor_sync(0xffffffffu, l1, 1);
    l1 += __shfl_xor_sync(0xffffffffu, l1, 2);
    const float inv0 = 1.0f / l0;
    const float inv1 = 1.0f / l1;

    const int r0 = q0 + w * 16 + gid;
    const int bb = bh >> 3;
    const int hh = bh & 7;
    const size_t o0 = ((size_t)bb * NN + r0) * C + hh * D;
    const size_t o1 = o0 + 8 * (size_t)C;
    #pragma unroll
    for (int nf = 0; nf < 8; nf++) {
        const int d = nf * 8 + tq * 2;
        *(uint32_t*)&g_AO16[o0 + d] = pack_h2(O[nf][0] * inv0, O[nf][1] * inv0);
        *(uint32_t*)&g_AO16[o1 + d] = pack_h2(O[nf][2] * inv1, O[nf][3] * inv1);
    }
}

// ---------------------------------------------------------------------------
// Output projection: 512 threads, 16 warps 4(M)x4(N), warp tile 32x32, BK=64.
// Same smem layout as gemm_body (RS=144; stage stride 55296).
// ---------------------------------------------------------------------------
__global__ __launch_bounds__(512, 1) void outproj_mma_kernel(
    const float* __restrict__ bo, float* __restrict__ out)
{
    extern __shared__ char dsm[];
    const uint32_t sb = smem_u32(dsm);
    const __half* A   = g_AO16;
    const __half* Wth = g_Wth + 3 * (size_t)C * C;
    const __half* Wtl = g_Wtl + 3 * (size_t)C * C;

    const int row0 = blockIdx.y * 128;
    const int col0 = blockIdx.x * 128;

    const int t    = threadIdx.x;
    const int lane = t & 31;
    const int gid  = lane >> 2;
    const int tq   = lane & 3;
    const int wm   = (t >> 5) >> 2;        // 0..3
    const int wn   = (t >> 5) & 3;         // 0..3

    #define ISSUE_STAGE(st, k0)                                                       \
    do {                                                                              \
        const uint32_t bb_ = sb + (uint32_t)(st) * 55296u;                            \
        _Pragma("unroll")                                                             \
        for (int c_ = 0; c_ < 2; c_++) {                                              \
            const int ch_ = t + c_ * 512;                                             \
            const int r_ = ch_ >> 3, q_ = ch_ & 7;                                    \
            const uint32_t d_ = (uint32_t)(r_ * RS + q_ * 16);                        \
            CP16(bb_ + d_,           A   + (size_t)(row0 + r_) * C + (k0) + q_ * 8);  \
            CP16(bb_ + 18432u + d_,  Wth + (size_t)(col0 + r_) * C + (k0) + q_ * 8);  \
            CP16(bb_ + 36864u + d_,  Wtl + (size_t)(col0 + r_) * C + (k0) + q_ * 8);  \
        }                                                                             \
        CP_COMMIT();                                                                  \
    } while (0)

    float acc[2][4][4];
    #pragma unroll
    for (int mf = 0; mf < 2; mf++)
        #pragma unroll
        for (int nf = 0; nf < 4; nf++)
            #pragma unroll
            for (int i = 0; i < 4; i++) acc[mf][nf][i] = 0.f;

    ISSUE_STAGE(0, 0);

    for (int it = 0; it < 8; it++) {
        CP_WAIT0();
        __syncthreads();
        if (it < 7) ISSUE_STAGE((it + 1) & 1, (it + 1) * 64);

        const char* stg = dsm + (it & 1) * 55296;
        #pragma unroll
        for (int kk = 0; kk < 4; kk++) {
            const int kb = (kk * 8 + tq) * 4;
            uint32_t Af[2][4];
            #pragma unroll
            for (int mf = 0; mf < 2; mf++) {
                const int m0 = wm * 32 + mf * 16;
                const uint32_t oa = (uint32_t)((m0 + gid) * RS + kb);
                const uint32_t ob = (uint32_t)((m0 + gid + 8) * RS + kb);
                Af[mf][0] = *(const uint32_t*)(stg + oa);
                Af[mf][1] = *(const uint32_t*)(stg + ob);
                Af[mf][2] = *(const uint32_t*)(stg + oa + 16);
                Af[mf][3] = *(const uint32_t*)(stg + ob + 16);
            }
            #pragma unroll
            for (int nf = 0; nf < 4; nf++) {
                const int n = wn * 32 + nf * 8 + gid;
                const uint32_t ow = (uint32_t)(n * RS + kb);
                uint32_t bh0 = *(const uint32_t*)(stg + 18432 + ow);
                uint32_t bh1 = *(const uint32_t*)(stg + 18432 + ow + 16);
                uint32_t bl0 = *(const uint32_t*)(stg + 36864 + ow);
                uint32_t bl1 = *(const uint32_t*)(stg + 36864 + ow + 16);
                #pragma unroll
                for (int mf = 0; mf < 2; mf++) {
                    MMAF16(acc[mf][nf], Af[mf][0], Af[mf][1], Af[mf][2], Af[mf][3], bh0, bh1);
                    MMAF16(acc[mf][nf], Af[mf][0], Af[mf][1], Af[mf][2], Af[mf][3], bl0, bl1);
                }
            }
        }
        __syncthreads();
    }
    #undef ISSUE_STAGE

    #pragma unroll
    for (int mf = 0; mf < 2; mf++) {
        const int rA = row0 + wm * 32 + mf * 16 + gid;
        const int rB = rA + 8;
        #pragma unroll
        for (int nf = 0; nf < 4; nf++) {
            const int cc = col0 + wn * 32 + nf * 8 + tq * 2;
            const float b0 = bo[cc], b1 = bo[cc + 1];
            *(float2*)&out[(size_t)rA * C + cc] =
                make_float2(acc[mf][nf][0] + b0, acc[mf][nf][1] + b1);
            *(float2*)&out[(size_t)rB * C + cc] =
                make_float2(acc[mf][nf][2] + b0, acc[mf][nf][3] + b1);
        }
    }
}

// ---------------------------------------------------------------------------
extern "C" void kernel_launch(void* const* d_in, const int* in_sizes, int n_in,
                              void* d_out, int out_size)
{
    const float* q     = (const float*)d_in[0];
    const float* kv    = (const float*)d_in[1];
    const float* pos_q = (const float*)d_in[2];
    const float* pos_k = (const float*)d_in[3];
    const float* Wq    = (const float*)d_in[4];
    const float* Wk    = (const float*)d_in[5];
    const float* Wv    = (const float*)d_in[6];
    const float* Wo    = (const float*)d_in[7];
    const float* bo    = (const float*)d_in[8];
    float* out = (float*)d_out;

    static bool attr_done = false;
    if (!attr_done) {
        cudaFuncSetAttribute(proj_mma_kernel, cudaFuncAttributeMaxDynamicSharedMemorySize, GEMM_SMEM);
        cudaFuncSetAttribute(outproj_mma_kernel, cudaFuncAttributeMaxDynamicSharedMemorySize, GEMM_SMEM);
        cudaFuncSetAttribute(attn_kernel, cudaFuncAttributeMaxDynamicSharedMemorySize, ATTN_SMEM);
        attr_done = true;
    }

    dim3 cgrid(128, 16, 6);
    convert_all<<<cgrid, 256>>>(q, kv, Wq, Wk, Wv, Wo);

    dim3 pgrid(C / 128, (B * NN) / 128, 3);
    proj_mma_kernel<<<pgrid, 256, GEMM_SMEM>>>(pos_q, pos_k);

    dim3 agrid(NN / 256, B * H);
    attn_kernel<<<agrid, 512, ATTN_SMEM>>>();

    dim3 ogrid(C / 128, (B * NN) / 128);
    outproj_mma_kernel<<<ogrid, 512, GEMM_SMEM>>>(bo, out);
}

// round 16
// speedup vs baseline: 1.3412x; 1.3412x over previous
#include <cuda_runtime.h>
#include <cuda_fp16.h>
#include <math.h>
#include <stdint.h>

#define B 2
#define NN 2048
#define C 512
#define H 8
#define D 64
#define SCALE_LOG2E 0.06376435597741051f      // 512^-0.5 * log2(e)

// -------- fp16 pre-converted inputs -----------------------------------------
__device__ __half g_q16 [B * NN * C];
__device__ __half g_kv16[B * NN * C];
__device__ __half g_Wt[4 * C * C];                       // W^T [n][k] fp16
// -------- attention operands -------------------------------------------------
__device__ __half g_Q [B * H * NN * D];                  // Q fp16, scale*log2e folded
__device__ __half g_K [B * H * NN * D];                  // K fp16
__device__ __half g_VT[B * H * D * NN];                  // [bh][d][n]
__device__ __half g_AO16[B * NN * C];                    // attention out, fp16

// ---------------------------------------------------------------------------
#define MMAF16(c, a0, a1, a2, a3, b0, b1)                                     \
    asm volatile("mma.sync.aligned.m16n8k16.row.col.f32.f16.f16.f32 "         \
        "{%0,%1,%2,%3}, {%4,%5,%6,%7}, {%8,%9}, {%0,%1,%2,%3};"               \
        : "+f"((c)[0]), "+f"((c)[1]), "+f"((c)[2]), "+f"((c)[3])              \
        : "r"(a0), "r"(a1), "r"(a2), "r"(a3), "r"(b0), "r"(b1))

#define MMAF16H(d0, d1, a0, a1, a2, a3, b0, b1)                               \
    asm volatile("mma.sync.aligned.m16n8k16.row.col.f16.f16.f16.f16 "         \
        "{%0,%1}, {%2,%3,%4,%5}, {%6,%7}, {%0,%1};"                           \
        : "+r"(d0), "+r"(d1)                                                  \
        : "r"(a0), "r"(a1), "r"(a2), "r"(a3), "r"(b0), "r"(b1))

#define CP16(dst, src) asm volatile(                                          \
    "cp.async.cg.shared.global [%0], [%1], 16;" :: "r"(dst), "l"(src))
#define CP_COMMIT() asm volatile("cp.async.commit_group;" ::: "memory")
#define CP_WAIT0()  asm volatile("cp.async.wait_group 0;" ::: "memory")
#define CP_WAIT1()  asm volatile("cp.async.wait_group 1;" ::: "memory")

__device__ __forceinline__ void ldmatrix_x4(uint32_t& r0, uint32_t& r1,
                                            uint32_t& r2, uint32_t& r3, uint32_t addr) {
    asm volatile("ldmatrix.sync.aligned.m8n8.x4.shared.b16 {%0,%1,%2,%3}, [%4];"
        : "=r"(r0), "=r"(r1), "=r"(r2), "=r"(r3) : "r"(addr));
}
__device__ __forceinline__ uint32_t ex2_h2(uint32_t x) {
    uint32_t r;
    asm("ex2.approx.f16x2 %0, %1;" : "=r"(r) : "r"(x));
    return r;
}
__device__ __forceinline__ uint32_t smem_u32(const void* p) {
    uint32_t a;
    asm("{ .reg .u64 t; cvta.to.shared.u64 t, %1; cvt.u32.u64 %0, t; }" : "=r"(a) : "l"(p));
    return a;
}
__device__ __forceinline__ uint32_t h2bits(__half2 h) {
    return *reinterpret_cast<uint32_t*>(&h);
}
__device__ __forceinline__ uint32_t pack_h2(float a, float b) {
    return h2bits(__floats2half2_rn(a, b));
}

// ---------------------------------------------------------------------------
// Fused pre-pass: z=0,1 -> q/kv fp32->fp16; z=2..5 -> W transpose (fp16)
// ---------------------------------------------------------------------------
__global__ __launch_bounds__(256) void convert_all(
    const float* __restrict__ q, const float* __restrict__ kv,
    const float* __restrict__ Wq, const float* __restrict__ Wk,
    const float* __restrict__ Wv, const float* __restrict__ Wo)
{
    const int z = blockIdx.z;
    if (z < 2) {
        const float* src = z ? kv : q;
        __half* dst = z ? g_kv16 : g_q16;
        const size_t i4 = ((size_t)blockIdx.y * 128 + blockIdx.x) * 256 + threadIdx.x;
        float4 v = ((const float4*)src)[i4];
        ((uint2*)dst)[i4] = make_uint2(pack_h2(v.x, v.y), pack_h2(v.z, v.w));
        return;
    }
    if (blockIdx.x >= 16) return;
    const int mat = z - 2;
    const float* W = (mat == 0) ? Wq : (mat == 1) ? Wk : (mat == 2) ? Wv : Wo;
    __half* outh = g_Wt + (size_t)mat * C * C;

    __shared__ float tile[32][33];
    const int k0 = blockIdx.y * 32;
    const int n0 = blockIdx.x * 32;
    const int tx = threadIdx.x & 31;
    const int ty = threadIdx.x >> 5;

    #pragma unroll
    for (int i = 0; i < 4; i++) {
        const int r = ty + i * 8;
        tile[r][tx] = W[(size_t)(k0 + r) * C + n0 + tx];
    }
    __syncthreads();

    const int n = threadIdx.x >> 3;
    const int p = threadIdx.x & 7;
    #pragma unroll
    for (int i = 0; i < 2; i++) {
        const int pp = p + i * 8;
        float f0 = tile[2 * pp][n];
        float f1 = tile[2 * pp + 1][n];
        *(uint32_t*)&outh[(size_t)(n0 + n) * C + k0 + 2 * pp] = pack_h2(f0, f1);
    }
}

// ---------------------------------------------------------------------------
// fp16 GEMM body (256 threads, warp tile 32x64), BK=64, single product.
// Row stride 144B. Stage: sA@0, sW@18432; stage stride 36864; 2 stages.
// ---------------------------------------------------------------------------
#define RS 144

__device__ __forceinline__ void gemm_body_f16(
    const __half* __restrict__ A, const __half* __restrict__ Wt,
    int row0, int col0, float acc[2][8][4], char* dsm)
{
    const uint32_t sb = smem_u32(dsm);
    const int t    = threadIdx.x;
    const int lane = t & 31;
    const int gid  = lane >> 2;
    const int tq   = lane & 3;
    const int wm   = (t >> 5) >> 1;
    const int wn   = (t >> 5) & 1;

    #define ISSUE_STAGE(st, k0)                                                       \
    do {                                                                              \
        const uint32_t bb_ = sb + (uint32_t)(st) * 36864u;                            \
        _Pragma("unroll")                                                             \
        for (int c_ = 0; c_ < 4; c_++) {                                              \
            const int ch_ = t + c_ * 256;                                             \
            const int r_ = ch_ >> 3, q_ = ch_ & 7;                                    \
            const uint32_t d_ = (uint32_t)(r_ * RS + q_ * 16);                        \
            CP16(bb_ + d_,           A  + (size_t)(row0 + r_) * C + (k0) + q_ * 8);   \
            CP16(bb_ + 18432u + d_,  Wt + (size_t)(col0 + r_) * C + (k0) + q_ * 8);   \
        }                                                                             \
        CP_COMMIT();                                                                  \
    } while (0)

    ISSUE_STAGE(0, 0);

    for (int it = 0; it < 8; it++) {
        CP_WAIT0();
        __syncthreads();
        if (it < 7) ISSUE_STAGE((it + 1) & 1, (it + 1) * 64);

        const char* stg = dsm + (it & 1) * 36864;
        #pragma unroll
        for (int kk = 0; kk < 4; kk++) {
            const int kb = (kk * 8 + tq) * 4;
            uint32_t Af[2][4];
            #pragma unroll
            for (int mf = 0; mf < 2; mf++) {
                const int m0 = wm * 32 + mf * 16;
                const uint32_t oa = (uint32_t)((m0 + gid) * RS + kb);
                const uint32_t ob = (uint32_t)((m0 + gid + 8) * RS + kb);
                Af[mf][0] = *(const uint32_t*)(stg + oa);
                Af[mf][1] = *(const uint32_t*)(stg + ob);
                Af[mf][2] = *(const uint32_t*)(stg + oa + 16);
                Af[mf][3] = *(const uint32_t*)(stg + ob + 16);
            }
            #pragma unroll
            for (int nf = 0; nf < 8; nf++) {
                const int n = wn * 64 + nf * 8 + gid;
                const uint32_t ow = (uint32_t)(n * RS + kb);
                uint32_t bh0 = *(const uint32_t*)(stg + 18432 + ow);
                uint32_t bh1 = *(const uint32_t*)(stg + 18432 + ow + 16);
                #pragma unroll
                for (int mf = 0; mf < 2; mf++) {
                    MMAF16(acc[mf][nf], Af[mf][0], Af[mf][1], Af[mf][2], Af[mf][3], bh0, bh1);
                }
            }
        }
        __syncthreads();
    }
    #undef ISSUE_STAGE
}

#define GEMM_SMEM 73728

// ---------------------------------------------------------------------------
// QKV projection (M128 tiles, 256 threads): z = 0:Q, 1:K, 2:V
// ---------------------------------------------------------------------------
__global__ __launch_bounds__(256, 2) void proj_mma_kernel(
    const float* __restrict__ pos_q, const float* __restrict__ pos_k)
{
    extern __shared__ char dsm[];
    const int which = blockIdx.z;
    const __half* A  = (which == 0) ? g_q16 : g_kv16;
    const __half* Wt = g_Wt + (size_t)which * C * C;

    const int row0 = blockIdx.y * 128;
    const int col0 = blockIdx.x * 128;

    float acc[2][8][4];
    #pragma unroll
    for (int mf = 0; mf < 2; mf++)
        #pragma unroll
        for (int nf = 0; nf < 8; nf++)
            #pragma unroll
            for (int i = 0; i < 4; i++) acc[mf][nf][i] = 0.f;

    gemm_body_f16(A, Wt, row0, col0, acc, dsm);

    const int lane = threadIdx.x & 31;
    const int gid = lane >> 2, tq = lane & 3;
    const int wm = (threadIdx.x >> 5) >> 1, wn = (threadIdx.x >> 5) & 1;

    #pragma unroll
    for (int mf = 0; mf < 2; mf++) {
        const int rA = row0 + wm * 32 + mf * 16 + gid;
        const int rB = rA + 8;
        const int bb = rA >> 11;
        const int nA = rA & (NN - 1);
        const int nB = rB & (NN - 1);
        #pragma unroll
        for (int nf = 0; nf < 8; nf++) {
            const int cc = col0 + wn * 64 + nf * 8 + tq * 2;
            const int hd = cc >> 6;
            const int dd = cc & 63;
            float v0 = acc[mf][nf][0], v1 = acc[mf][nf][1];
            float v2 = acc[mf][nf][2], v3 = acc[mf][nf][3];

            if (which == 0) {
                float2 pA = *(const float2*)&pos_q[((size_t)bb * NN + nA) * D + dd];
                float2 pB = *(const float2*)&pos_q[((size_t)bb * NN + nB) * D + dd];
                v0 = (v0 + pA.x) * SCALE_LOG2E; v1 = (v1 + pA.y) * SCALE_LOG2E;
                v2 = (v2 + pB.x) * SCALE_LOG2E; v3 = (v3 + pB.y) * SCALE_LOG2E;
                const size_t dA = (((size_t)bb * H + hd) * NN + nA) * D + dd;
                const size_t dB = (((size_t)bb * H + hd) * NN + nB) * D + dd;
                *(uint32_t*)&g_Q[dA] = pack_h2(v0, v1);
                *(uint32_t*)&g_Q[dB] = pack_h2(v2, v3);
            } else if (which == 1) {
                float2 pA = *(const float2*)&pos_k[((size_t)bb * NN + nA) * D + dd];
                float2 pB = *(const float2*)&pos_k[((size_t)bb * NN + nB) * D + dd];
                v0 += pA.x; v1 += pA.y; v2 += pB.x; v3 += pB.y;
                const size_t dA = (((size_t)bb * H + hd) * NN + nA) * D + dd;
                const size_t dB = (((size_t)bb * H + hd) * NN + nB) * D + dd;
                *(uint32_t*)&g_K[dA] = pack_h2(v0, v1);
                *(uint32_t*)&g_K[dB] = pack_h2(v2, v3);
            } else {
                const size_t base = ((size_t)bb * H + hd) * D;
                g_VT[(base + dd)     * NN + nA] = __float2half(v0);
                g_VT[(base + dd + 1) * NN + nA] = __float2half(v1);
                g_VT[(base + dd)     * NN + nB] = __float2half(v2);
                g_VT[(base + dd + 1) * NN + nB] = __float2half(v3);
            }
        }
    }
}

// ---------------------------------------------------------------------------
// FA2 flash attention: 512 threads, q-tile 256, key tile 64, 3-stage pipeline.
// ---------------------------------------------------------------------------
#define TK 64
#define TSWZ(r, cb) ((r) * 128 + ((cb) ^ (((r) & 7) << 4)))
#define ATTN_SMEM 49152

__global__ __launch_bounds__(512, 1) void attn_kernel()
{
    extern __shared__ char dsm[];
    const uint32_t sb = smem_u32(dsm);

    const int t    = threadIdx.x;
    const int w    = t >> 5;
    const int lane = t & 31;
    const int gid  = lane >> 2;
    const int tq   = lane & 3;
    const int bh   = blockIdx.y;
    const int q0   = blockIdx.x * 256;

    const int rch = t >> 3;
    const int cch = t & 7;

    const int lg = lane >> 3;
    const int lr = lane & 7;
    const int lx = lr << 4;
    const uint32_t kSel = (uint32_t)((lg & 1) << 4);
    const uint32_t rowOff = (uint32_t)((((lg >> 1) << 3) + lr) * 128);

    #define ISSUE_TILE(st, j0)                                                        \
    do {                                                                              \
        const uint32_t bb_ = sb + (uint32_t)(st) * 16384u;                            \
        const uint32_t d_ = TSWZ(rch, cch * 16);                                      \
        CP16(bb_ + d_,          g_K  + ((size_t)bh * NN + (j0) + rch) * D + cch * 8); \
        CP16(bb_ + 8192u + d_,  g_VT + ((size_t)bh * D + rch) * NN + (j0) + cch * 8); \
        CP_COMMIT();                                                                  \
    } while (0)

    uint32_t Ah[4][4];
    {
        const int r0 = q0 + w * 16 + gid;
        const __half* qh0 = g_Q + ((size_t)bh * NN + r0) * D;
        const __half* qh1 = qh0 + 8 * D;
        #pragma unroll
        for (int ks = 0; ks < 4; ks++) {
            const int k = ks * 16 + tq * 2;
            Ah[ks][0] = *(const uint32_t*)(qh0 + k);
            Ah[ks][1] = *(const uint32_t*)(qh1 + k);
            Ah[ks][2] = *(const uint32_t*)(qh0 + k + 8);
            Ah[ks][3] = *(const uint32_t*)(qh1 + k + 8);
        }
    }

    float O[8][4];
    #pragma unroll
    for (int nf = 0; nf < 8; nf++)
        #pragma unroll
        for (int i = 0; i < 4; i++) O[nf][i] = 0.f;
    float l0 = 0.f, l1 = 0.f;

    ISSUE_TILE(0, 0);
    ISSUE_TILE(1, TK);

    int stc = 0;
    for (int jt = 0; jt < NN / TK; jt++) {
        CP_WAIT1();
        __syncthreads();
        if (jt + 2 < NN / TK) {
            int sti = stc + 2; if (sti >= 3) sti -= 3;
            ISSUE_TILE(sti, (jt + 2) * TK);
        }

        const uint32_t stg = sb + (uint32_t)stc * 16384u;

        uint32_t sh[8][2];
        #pragma unroll
        for (int nf = 0; nf < 8; nf++) { sh[nf][0] = 0u; sh[nf][1] = 0u; }

        #pragma unroll
        for (int ks = 0; ks < 4; ks++) {
            const uint32_t kcb = ((uint32_t)(ks * 32) + kSel) ^ (uint32_t)lx;
            #pragma unroll
            for (int np = 0; np < 4; np++) {
                const uint32_t addr = stg + (uint32_t)(np * 2048) + rowOff + kcb;
                uint32_t b0, b1, b2, b3;
                ldmatrix_x4(b0, b1, b2, b3, addr);
                MMAF16H(sh[2 * np][0],     sh[2 * np][1],
                        Ah[ks][0], Ah[ks][1], Ah[ks][2], Ah[ks][3], b0, b1);
                MMAF16H(sh[2 * np + 1][0], sh[2 * np + 1][1],
                        Ah[ks][0], Ah[ks][1], Ah[ks][2], Ah[ks][3], b2, b3);
            }
        }

        uint32_t ph[8][2];
        __half2 la0 = __floats2half2_rn(0.f, 0.f);
        __half2 la1 = la0;
        #pragma unroll
        for (int nf = 0; nf < 8; nf++) {
            ph[nf][0] = ex2_h2(sh[nf][0]);
            ph[nf][1] = ex2_h2(sh[nf][1]);
            la0 = __hadd2(la0, *(__half2*)&ph[nf][0]);
            la1 = __hadd2(la1, *(__half2*)&ph[nf][1]);
        }
        {
            float2 f0 = __half22float2(la0);
            float2 f1 = __half22float2(la1);
            l0 += f0.x + f0.y;
            l1 += f1.x + f1.y;
        }

        #pragma unroll
        for (int ks = 0; ks < 4; ks++) {
            const uint32_t a0 = ph[2 * ks][0],     a1 = ph[2 * ks][1];
            const uint32_t a2 = ph[2 * ks + 1][0], a3 = ph[2 * ks + 1][1];
            const uint32_t kcb = ((uint32_t)(ks * 32) + kSel) ^ (uint32_t)lx;
            #pragma unroll
            for (int np = 0; np < 4; np++) {
                const uint32_t addr = stg + 8192u + (uint32_t)(np * 2048) + rowOff + kcb;
                uint32_t bv0, bv1, bv2, bv3;
                ldmatrix_x4(bv0, bv1, bv2, bv3, addr);
                MMAF16(O[2 * np],     a0, a1, a2, a3, bv0, bv1);
                MMAF16(O[2 * np + 1], a0, a1, a2, a3, bv2, bv3);
            }
        }
        __syncthreads();
        if (++stc == 3) stc = 0;
    }
    #undef ISSUE_TILE

    l0 += __shfl_xor_sync(0xffffffffu, l0, 1);
    l0 += __shfl_xor_sync(0xffffffffu, l0, 2);
    l1 += __shfl_xor_sync(0xffffffffu, l1, 1);
    l1 += __shfl_xor_sync(0xffffffffu, l1, 2);
    const float inv0 = 1.0f / l0;
    const float inv1 = 1.0f / l1;

    const int r0 = q0 + w * 16 + gid;
    const int bb = bh >> 3;
    const int hh = bh & 7;
    const size_t o0 = ((size_t)bb * NN + r0) * C + hh * D;
    const size_t o1 = o0 + 8 * (size_t)C;
    #pragma unroll
    for (int nf = 0; nf < 8; nf++) {
        const int d = nf * 8 + tq * 2;
        *(uint32_t*)&g_AO16[o0 + d] = pack_h2(O[nf][0] * inv0, O[nf][1] * inv0);
        *(uint32_t*)&g_AO16[o1 + d] = pack_h2(O[nf][2] * inv1, O[nf][3] * inv1);
    }
}

// ---------------------------------------------------------------------------
// Output projection (M128 tiles, 256 threads): out = AO @ Wo + bo
// ---------------------------------------------------------------------------
__global__ __launch_bounds__(256, 2) void outproj_mma_kernel(
    const float* __restrict__ bo, float* __restrict__ out)
{
    extern __shared__ char dsm[];
    const int row0 = blockIdx.y * 128;
    const int col0 = blockIdx.x * 128;

    float acc[2][8][4];
    #pragma unroll
    for (int mf = 0; mf < 2; mf++)
        #pragma unroll
        for (int nf = 0; nf < 8; nf++)
            #pragma unroll
            for (int i = 0; i < 4; i++) acc[mf][nf][i] = 0.f;

    gemm_body_f16(g_AO16, g_Wt + 3 * (size_t)C * C, row0, col0, acc, dsm);

    const int lane = threadIdx.x & 31;
    const int gid = lane >> 2, tq = lane & 3;
    const int wm = (threadIdx.x >> 5) >> 1, wn = (threadIdx.x >> 5) & 1;

    #pragma unroll
    for (int mf = 0; mf < 2; mf++) {
        const int rA = row0 + wm * 32 + mf * 16 + gid;
        const int rB = rA + 8;
        #pragma unroll
        for (int nf = 0; nf < 8; nf++) {
            const int cc = col0 + wn * 64 + nf * 8 + tq * 2;
            const float b0 = bo[cc], b1 = bo[cc + 1];
            *(float2*)&out[(size_t)rA * C + cc] =
                make_float2(acc[mf][nf][0] + b0, acc[mf][nf][1] + b1);
            *(float2*)&out[(size_t)rB * C + cc] =
                make_float2(acc[mf][nf][2] + b0, acc[mf][nf][3] + b1);
        }
    }
}

// ---------------------------------------------------------------------------
extern "C" void kernel_launch(void* const* d_in, const int* in_sizes, int n_in,
                              void* d_out, int out_size)
{
    const float* q     = (const float*)d_in[0];
    const float* kv    = (const float*)d_in[1];
    const float* pos_q = (const float*)d_in[2];
    const float* pos_k = (const float*)d_in[3];
    const float* Wq    = (const float*)d_in[4];
    const float* Wk    = (const float*)d_in[5];
    const float* Wv    = (const float*)d_in[6];
    const float* Wo    = (const float*)d_in[7];
    const float* bo    = (const float*)d_in[8];
    float* out = (float*)d_out;

    static bool attr_done = false;
    if (!attr_done) {
        cudaFuncSetAttribute(proj_mma_kernel, cudaFuncAttributeMaxDynamicSharedMemorySize, GEMM_SMEM);
        cudaFuncSetAttribute(outproj_mma_kernel, cudaFuncAttributeMaxDynamicSharedMemorySize, GEMM_SMEM);
        cudaFuncSetAttribute(attn_kernel, cudaFuncAttributeMaxDynamicSharedMemorySize, ATTN_SMEM);
        attr_done = true;
    }

    dim3 cgrid(128, 16, 6);
    convert_all<<<cgrid, 256>>>(q, kv, Wq, Wk, Wv, Wo);

    dim3 pgrid(C / 128, (B * NN) / 128, 3);
    proj_mma_kernel<<<pgrid, 256, GEMM_SMEM>>>(pos_q, pos_k);

    dim3 agrid(NN / 256, B * H);
    attn_kernel<<<agrid, 512, ATTN_SMEM>>>();

    dim3 ogrid(C / 128, (B * NN) / 128);
    outproj_mma_kernel<<<ogrid, 256, GEMM_SMEM>>>(bo, out);
}

// round 17
// speedup vs baseline: 1.3962x; 1.0410x over previous
#include <cuda_runtime.h>
#include <cuda_fp16.h>
#include <math.h>
#include <stdint.h>

#define B 2
#define NN 2048
#define C 512
#define H 8
#define D 64
#define SCALE_LOG2E 0.06376435597741051f      // 512^-0.5 * log2(e)

// -------- fp16 pre-converted inputs -----------------------------------------
__device__ __half g_q16 [B * NN * C];
__device__ __half g_kv16[B * NN * C];
__device__ __half g_Wt[4 * C * C];                       // W^T [n][k] fp16
// -------- attention operands -------------------------------------------------
__device__ __half g_Q [B * H * NN * D];                  // Q fp16, scale*log2e folded
__device__ __half g_K [B * H * NN * D];                  // K fp16
__device__ __half g_VT[B * H * D * NN];                  // [bh][d][n]
__device__ __half g_AO16[B * NN * C];                    // attention out, fp16

// ---------------------------------------------------------------------------
#define MMAF16(c, a0, a1, a2, a3, b0, b1)                                     \
    asm volatile("mma.sync.aligned.m16n8k16.row.col.f32.f16.f16.f32 "         \
        "{%0,%1,%2,%3}, {%4,%5,%6,%7}, {%8,%9}, {%0,%1,%2,%3};"               \
        : "+f"((c)[0]), "+f"((c)[1]), "+f"((c)[2]), "+f"((c)[3])              \
        : "r"(a0), "r"(a1), "r"(a2), "r"(a3), "r"(b0), "r"(b1))

#define MMAF16H(d0, d1, a0, a1, a2, a3, b0, b1)                               \
    asm volatile("mma.sync.aligned.m16n8k16.row.col.f16.f16.f16.f16 "         \
        "{%0,%1}, {%2,%3,%4,%5}, {%6,%7}, {%0,%1};"                           \
        : "+r"(d0), "+r"(d1)                                                  \
        : "r"(a0), "r"(a1), "r"(a2), "r"(a3), "r"(b0), "r"(b1))

#define CP16(dst, src) asm volatile(                                          \
    "cp.async.cg.shared.global [%0], [%1], 16;" :: "r"(dst), "l"(src))
#define CP_COMMIT() asm volatile("cp.async.commit_group;" ::: "memory")
#define CP_WAIT0()  asm volatile("cp.async.wait_group 0;" ::: "memory")
#define CP_WAIT1()  asm volatile("cp.async.wait_group 1;" ::: "memory")

__device__ __forceinline__ void ldmatrix_x4(uint32_t& r0, uint32_t& r1,
                                            uint32_t& r2, uint32_t& r3, uint32_t addr) {
    asm volatile("ldmatrix.sync.aligned.m8n8.x4.shared.b16 {%0,%1,%2,%3}, [%4];"
        : "=r"(r0), "=r"(r1), "=r"(r2), "=r"(r3) : "r"(addr));
}
__device__ __forceinline__ uint32_t ex2_h2(uint32_t x) {
    uint32_t r;
    asm("ex2.approx.f16x2 %0, %1;" : "=r"(r) : "r"(x));
    return r;
}
__device__ __forceinline__ uint32_t smem_u32(const void* p) {
    uint32_t a;
    asm("{ .reg .u64 t; cvta.to.shared.u64 t, %1; cvt.u32.u64 %0, t; }" : "=r"(a) : "l"(p));
    return a;
}
__device__ __forceinline__ uint32_t h2bits(__half2 h) {
    return *reinterpret_cast<uint32_t*>(&h);
}
__device__ __forceinline__ uint32_t pack_h2(float a, float b) {
    return h2bits(__floats2half2_rn(a, b));
}

// ---------------------------------------------------------------------------
// Fused pre-pass: z=0,1 -> q/kv fp32->fp16; z=2..5 -> W transpose (fp16)
// ---------------------------------------------------------------------------
__global__ __launch_bounds__(256) void convert_all(
    const float* __restrict__ q, const float* __restrict__ kv,
    const float* __restrict__ Wq, const float* __restrict__ Wk,
    const float* __restrict__ Wv, const float* __restrict__ Wo)
{
    const int z = blockIdx.z;
    if (z < 2) {
        const float* src = z ? kv : q;
        __half* dst = z ? g_kv16 : g_q16;
        const size_t i4 = ((size_t)blockIdx.y * 128 + blockIdx.x) * 256 + threadIdx.x;
        float4 v = ((const float4*)src)[i4];
        ((uint2*)dst)[i4] = make_uint2(pack_h2(v.x, v.y), pack_h2(v.z, v.w));
        return;
    }
    if (blockIdx.x >= 16) return;
    const int mat = z - 2;
    const float* W = (mat == 0) ? Wq : (mat == 1) ? Wk : (mat == 2) ? Wv : Wo;
    __half* outh = g_Wt + (size_t)mat * C * C;

    __shared__ float tile[32][33];
    const int k0 = blockIdx.y * 32;
    const int n0 = blockIdx.x * 32;
    const int tx = threadIdx.x & 31;
    const int ty = threadIdx.x >> 5;

    #pragma unroll
    for (int i = 0; i < 4; i++) {
        const int r = ty + i * 8;
        tile[r][tx] = W[(size_t)(k0 + r) * C + n0 + tx];
    }
    __syncthreads();

    const int n = threadIdx.x >> 3;
    const int p = threadIdx.x & 7;
    #pragma unroll
    for (int i = 0; i < 2; i++) {
        const int pp = p + i * 8;
        float f0 = tile[2 * pp][n];
        float f1 = tile[2 * pp + 1][n];
        *(uint32_t*)&outh[(size_t)(n0 + n) * C + k0 + 2 * pp] = pack_h2(f0, f1);
    }
}

// ---------------------------------------------------------------------------
// fp16 GEMM body (256 threads, warp tile 32x64), BK=64, single product.
// Row stride 144B. Stage: sA@0, sW@18432; stage stride 36864; 2 stages.
// Single barrier per iteration (top): reads of stage it-1 are complete for
// all threads once the iter-it barrier passes, so the it+1 prefetch is safe.
// ---------------------------------------------------------------------------
#define RS 144

__device__ __forceinline__ void gemm_body_f16(
    const __half* __restrict__ A, const __half* __restrict__ Wt,
    int row0, int col0, float acc[2][8][4], char* dsm)
{
    const uint32_t sb = smem_u32(dsm);
    const int t    = threadIdx.x;
    const int lane = t & 31;
    const int gid  = lane >> 2;
    const int tq   = lane & 3;
    const int wm   = (t >> 5) >> 1;
    const int wn   = (t >> 5) & 1;

    #define ISSUE_STAGE(st, k0)                                                       \
    do {                                                                              \
        const uint32_t bb_ = sb + (uint32_t)(st) * 36864u;                            \
        _Pragma("unroll")                                                             \
        for (int c_ = 0; c_ < 4; c_++) {                                              \
            const int ch_ = t + c_ * 256;                                             \
            const int r_ = ch_ >> 3, q_ = ch_ & 7;                                    \
            const uint32_t d_ = (uint32_t)(r_ * RS + q_ * 16);                        \
            CP16(bb_ + d_,           A  + (size_t)(row0 + r_) * C + (k0) + q_ * 8);   \
            CP16(bb_ + 18432u + d_,  Wt + (size_t)(col0 + r_) * C + (k0) + q_ * 8);   \
        }                                                                             \
        CP_COMMIT();                                                                  \
    } while (0)

    ISSUE_STAGE(0, 0);

    for (int it = 0; it < 8; it++) {
        CP_WAIT0();
        __syncthreads();
        if (it < 7) ISSUE_STAGE((it + 1) & 1, (it + 1) * 64);

        const char* stg = dsm + (it & 1) * 36864;
        #pragma unroll
        for (int kk = 0; kk < 4; kk++) {
            const int kb = (kk * 8 + tq) * 4;
            uint32_t Af[2][4];
            #pragma unroll
            for (int mf = 0; mf < 2; mf++) {
                const int m0 = wm * 32 + mf * 16;
                const uint32_t oa = (uint32_t)((m0 + gid) * RS + kb);
                const uint32_t ob = (uint32_t)((m0 + gid + 8) * RS + kb);
                Af[mf][0] = *(const uint32_t*)(stg + oa);
                Af[mf][1] = *(const uint32_t*)(stg + ob);
                Af[mf][2] = *(const uint32_t*)(stg + oa + 16);
                Af[mf][3] = *(const uint32_t*)(stg + ob + 16);
            }
            #pragma unroll
            for (int nf = 0; nf < 8; nf++) {
                const int n = wn * 64 + nf * 8 + gid;
                const uint32_t ow = (uint32_t)(n * RS + kb);
                uint32_t bh0 = *(const uint32_t*)(stg + 18432 + ow);
                uint32_t bh1 = *(const uint32_t*)(stg + 18432 + ow + 16);
                #pragma unroll
                for (int mf = 0; mf < 2; mf++) {
                    MMAF16(acc[mf][nf], Af[mf][0], Af[mf][1], Af[mf][2], Af[mf][3], bh0, bh1);
                }
            }
        }
    }
    #undef ISSUE_STAGE
}

#define GEMM_SMEM 73728

// ---------------------------------------------------------------------------
// QKV projection (M128 tiles, 256 threads): z = 0:Q, 1:K, 2:V
// ---------------------------------------------------------------------------
__global__ __launch_bounds__(256, 2) void proj_mma_kernel(
    const float* __restrict__ pos_q, const float* __restrict__ pos_k)
{
    extern __shared__ char dsm[];
    const int which = blockIdx.z;
    const __half* A  = (which == 0) ? g_q16 : g_kv16;
    const __half* Wt = g_Wt + (size_t)which * C * C;

    const int row0 = blockIdx.y * 128;
    const int col0 = blockIdx.x * 128;

    float acc[2][8][4];
    #pragma unroll
    for (int mf = 0; mf < 2; mf++)
        #pragma unroll
        for (int nf = 0; nf < 8; nf++)
            #pragma unroll
            for (int i = 0; i < 4; i++) acc[mf][nf][i] = 0.f;

    gemm_body_f16(A, Wt, row0, col0, acc, dsm);

    const int lane = threadIdx.x & 31;
    const int gid = lane >> 2, tq = lane & 3;
    const int wm = (threadIdx.x >> 5) >> 1, wn = (threadIdx.x >> 5) & 1;

    #pragma unroll
    for (int mf = 0; mf < 2; mf++) {
        const int rA = row0 + wm * 32 + mf * 16 + gid;
        const int rB = rA + 8;
        const int bb = rA >> 11;
        const int nA = rA & (NN - 1);
        const int nB = rB & (NN - 1);
        #pragma unroll
        for (int nf = 0; nf < 8; nf++) {
            const int cc = col0 + wn * 64 + nf * 8 + tq * 2;
            const int hd = cc >> 6;
            const int dd = cc & 63;
            float v0 = acc[mf][nf][0], v1 = acc[mf][nf][1];
            float v2 = acc[mf][nf][2], v3 = acc[mf][nf][3];

            if (which == 0) {
                float2 pA = *(const float2*)&pos_q[((size_t)bb * NN + nA) * D + dd];
                float2 pB = *(const float2*)&pos_q[((size_t)bb * NN + nB) * D + dd];
                v0 = (v0 + pA.x) * SCALE_LOG2E; v1 = (v1 + pA.y) * SCALE_LOG2E;
                v2 = (v2 + pB.x) * SCALE_LOG2E; v3 = (v3 + pB.y) * SCALE_LOG2E;
                const size_t dA = (((size_t)bb * H + hd) * NN + nA) * D + dd;
                const size_t dB = (((size_t)bb * H + hd) * NN + nB) * D + dd;
                *(uint32_t*)&g_Q[dA] = pack_h2(v0, v1);
                *(uint32_t*)&g_Q[dB] = pack_h2(v2, v3);
            } else if (which == 1) {
                float2 pA = *(const float2*)&pos_k[((size_t)bb * NN + nA) * D + dd];
                float2 pB = *(const float2*)&pos_k[((size_t)bb * NN + nB) * D + dd];
                v0 += pA.x; v1 += pA.y; v2 += pB.x; v3 += pB.y;
                const size_t dA = (((size_t)bb * H + hd) * NN + nA) * D + dd;
                const size_t dB = (((size_t)bb * H + hd) * NN + nB) * D + dd;
                *(uint32_t*)&g_K[dA] = pack_h2(v0, v1);
                *(uint32_t*)&g_K[dB] = pack_h2(v2, v3);
            } else {
                const size_t base = ((size_t)bb * H + hd) * D;
                g_VT[(base + dd)     * NN + nA] = __float2half(v0);
                g_VT[(base + dd + 1) * NN + nA] = __float2half(v1);
                g_VT[(base + dd)     * NN + nB] = __float2half(v2);
                g_VT[(base + dd + 1) * NN + nB] = __float2half(v3);
            }
        }
    }
}

// ---------------------------------------------------------------------------
// FA2 flash attention: 512 threads, q-tile 256.
// 128-key super-tiles (two 64-key sub-tiles per stage), 3 stages, wait1,
// single barrier per super-tile. S in fp16 accum -> ex2.f16x2 on fragments.
// Stage: K0@0, K1@8192, V0@16384, V1@24576; stride 32768; 3 stages = 98304.
// ---------------------------------------------------------------------------
#define TSWZ(r, cb) ((r) * 128 + ((cb) ^ (((r) & 7) << 4)))
#define ATTN_SMEM 98304

__global__ __launch_bounds__(512, 1) void attn_kernel()
{
    extern __shared__ char dsm[];
    const uint32_t sb = smem_u32(dsm);

    const int t    = threadIdx.x;
    const int w    = t >> 5;
    const int lane = t & 31;
    const int gid  = lane >> 2;
    const int tq   = lane & 3;
    const int bh   = blockIdx.y;
    const int q0   = blockIdx.x * 256;

    const int rch = t >> 3;           // 0..63
    const int cch = t & 7;

    const int lg = lane >> 3;
    const int lr = lane & 7;
    const int lx = lr << 4;
    const uint32_t kSel = (uint32_t)((lg & 1) << 4);
    const uint32_t rowOff = (uint32_t)((((lg >> 1) << 3) + lr) * 128);

    #define ISSUE_TILE(st, j0)                                                        \
    do {                                                                              \
        const uint32_t bb_ = sb + (uint32_t)(st) * 32768u;                            \
        const uint32_t d_ = TSWZ(rch, cch * 16);                                      \
        _Pragma("unroll")                                                             \
        for (int h_ = 0; h_ < 2; h_++) {                                              \
            CP16(bb_ + (uint32_t)(h_ * 8192) + d_,                                    \
                 g_K  + ((size_t)bh * NN + (j0) + h_ * 64 + rch) * D + cch * 8);      \
            CP16(bb_ + 16384u + (uint32_t)(h_ * 8192) + d_,                           \
                 g_VT + ((size_t)bh * D + rch) * NN + (j0) + h_ * 64 + cch * 8);      \
        }                                                                             \
        CP_COMMIT();                                                                  \
    } while (0)

    uint32_t Ah[4][4];
    {
        const int r0 = q0 + w * 16 + gid;
        const __half* qh0 = g_Q + ((size_t)bh * NN + r0) * D;
        const __half* qh1 = qh0 + 8 * D;
        #pragma unroll
        for (int ks = 0; ks < 4; ks++) {
            const int k = ks * 16 + tq * 2;
            Ah[ks][0] = *(const uint32_t*)(qh0 + k);
            Ah[ks][1] = *(const uint32_t*)(qh1 + k);
            Ah[ks][2] = *(const uint32_t*)(qh0 + k + 8);
            Ah[ks][3] = *(const uint32_t*)(qh1 + k + 8);
        }
    }

    float O[8][4];
    #pragma unroll
    for (int nf = 0; nf < 8; nf++)
        #pragma unroll
        for (int i = 0; i < 4; i++) O[nf][i] = 0.f;
    float l0 = 0.f, l1 = 0.f;

    ISSUE_TILE(0, 0);
    ISSUE_TILE(1, 128);

    int stc = 0;
    for (int jt = 0; jt < NN / 128; jt++) {
        CP_WAIT1();
        __syncthreads();
        if (jt + 2 < NN / 128) {
            int sti = stc + 2; if (sti >= 3) sti -= 3;
            ISSUE_TILE(sti, (jt + 2) * 128);
        }

        const uint32_t stage = sb + (uint32_t)stc * 32768u;

        #pragma unroll
        for (int kh = 0; kh < 2; kh++) {
            const uint32_t stgK = stage + (uint32_t)(kh * 8192);
            const uint32_t stgV = stage + 16384u + (uint32_t)(kh * 8192);

            // ---- S = Q.K, fp16 accumulator ----
            uint32_t sh[8][2];
            #pragma unroll
            for (int nf = 0; nf < 8; nf++) { sh[nf][0] = 0u; sh[nf][1] = 0u; }

            #pragma unroll
            for (int ks = 0; ks < 4; ks++) {
                const uint32_t kcb = ((uint32_t)(ks * 32) + kSel) ^ (uint32_t)lx;
                #pragma unroll
                for (int np = 0; np < 4; np++) {
                    const uint32_t addr = stgK + (uint32_t)(np * 2048) + rowOff + kcb;
                    uint32_t b0, b1, b2, b3;
                    ldmatrix_x4(b0, b1, b2, b3, addr);
                    MMAF16H(sh[2 * np][0],     sh[2 * np][1],
                            Ah[ks][0], Ah[ks][1], Ah[ks][2], Ah[ks][3], b0, b1);
                    MMAF16H(sh[2 * np + 1][0], sh[2 * np + 1][1],
                            Ah[ks][0], Ah[ks][1], Ah[ks][2], Ah[ks][3], b2, b3);
                }
            }

            // ---- softmax: p = 2^s on fragments ----
            uint32_t ph[8][2];
            __half2 la0 = __floats2half2_rn(0.f, 0.f);
            __half2 la1 = la0;
            #pragma unroll
            for (int nf = 0; nf < 8; nf++) {
                ph[nf][0] = ex2_h2(sh[nf][0]);
                ph[nf][1] = ex2_h2(sh[nf][1]);
                la0 = __hadd2(la0, *(__half2*)&ph[nf][0]);
                la1 = __hadd2(la1, *(__half2*)&ph[nf][1]);
            }
            {
                float2 f0 = __half22float2(la0);
                float2 f1 = __half22float2(la1);
                l0 += f0.x + f0.y;
                l1 += f1.x + f1.y;
            }

            // ---- O += P.V ----
            #pragma unroll
            for (int ks = 0; ks < 4; ks++) {
                const uint32_t a0 = ph[2 * ks][0],     a1 = ph[2 * ks][1];
                const uint32_t a2 = ph[2 * ks + 1][0], a3 = ph[2 * ks + 1][1];
                const uint32_t kcb = ((uint32_t)(ks * 32) + kSel) ^ (uint32_t)lx;
                #pragma unroll
                for (int np = 0; np < 4; np++) {
                    const uint32_t addr = stgV + (uint32_t)(np * 2048) + rowOff + kcb;
                    uint32_t bv0, bv1, bv2, bv3;
                    ldmatrix_x4(bv0, bv1, bv2, bv3, addr);
                    MMAF16(O[2 * np],     a0, a1, a2, a3, bv0, bv1);
                    MMAF16(O[2 * np + 1], a0, a1, a2, a3, bv2, bv3);
                }
            }
        }
        if (++stc == 3) stc = 0;
    }
    #undef ISSUE_TILE

    l0 += __shfl_xor_sync(0xffffffffu, l0, 1);
    l0 += __shfl_xor_sync(0xffffffffu, l0, 2);
    l1 += __shfl_xor_sync(0xffffffffu, l1, 1);
    l1 += __shfl_xor_sync(0xffffffffu, l1, 2);
    const float inv0 = 1.0f / l0;
    const float inv1 = 1.0f / l1;

    const int r0 = q0 + w * 16 + gid;
    const int bb = bh >> 3;
    const int hh = bh & 7;
    const size_t o0 = ((size_t)bb * NN + r0) * C + hh * D;
    const size_t o1 = o0 + 8 * (size_t)C;
    #pragma unroll
    for (int nf = 0; nf < 8; nf++) {
        const int d = nf * 8 + tq * 2;
        *(uint32_t*)&g_AO16[o0 + d] = pack_h2(O[nf][0] * inv0, O[nf][1] * inv0);
        *(uint32_t*)&g_AO16[o1 + d] = pack_h2(O[nf][2] * inv1, O[nf][3] * inv1);
    }
}

// ---------------------------------------------------------------------------
// Output projection (M128 tiles, 256 threads): out = AO @ Wo + bo
// ---------------------------------------------------------------------------
__global__ __launch_bounds__(256, 2) void outproj_mma_kernel(
    const float* __restrict__ bo, float* __restrict__ out)
{
    extern __shared__ char dsm[];
    const int row0 = blockIdx.y * 128;
    const int col0 = blockIdx.x * 128;

    float acc[2][8][4];
    #pragma unroll
    for (int mf = 0; mf < 2; mf++)
        #pragma unroll
        for (int nf = 0; nf < 8; nf++)
            #pragma unroll
            for (int i = 0; i < 4; i++) acc[mf][nf][i] = 0.f;

    gemm_body_f16(g_AO16, g_Wt + 3 * (size_t)C * C, row0, col0, acc, dsm);

    const int lane = threadIdx.x & 31;
    const int gid = lane >> 2, tq = lane & 3;
    const int wm = (threadIdx.x >> 5) >> 1, wn = (threadIdx.x >> 5) & 1;

    #pragma unroll
    for (int mf = 0; mf < 2; mf++) {
        const int rA = row0 + wm * 32 + mf * 16 + gid;
        const int rB = rA + 8;
        #pragma unroll
        for (int nf = 0; nf < 8; nf++) {
            const int cc = col0 + wn * 64 + nf * 8 + tq * 2;
            const float b0 = bo[cc], b1 = bo[cc + 1];
            *(float2*)&out[(size_t)rA * C + cc] =
                make_float2(acc[mf][nf][0] + b0, acc[mf][nf][1] + b1);
            *(float2*)&out[(size_t)rB * C + cc] =
                make_float2(acc[mf][nf][2] + b0, acc[mf][nf][3] + b1);
        }
    }
}

// ---------------------------------------------------------------------------
extern "C" void kernel_launch(void* const* d_in, const int* in_sizes, int n_in,
                              void* d_out, int out_size)
{
    const float* q     = (const float*)d_in[0];
    const float* kv    = (const float*)d_in[1];
    const float* pos_q = (const float*)d_in[2];
    const float* pos_k = (const float*)d_in[3];
    const float* Wq    = (const float*)d_in[4];
    const float* Wk    = (const float*)d_in[5];
    const float* Wv    = (const float*)d_in[6];
    const float* Wo    = (const float*)d_in[7];
    const float* bo    = (const float*)d_in[8];
    float* out = (float*)d_out;

    static bool attr_done = false;
    if (!attr_done) {
        cudaFuncSetAttribute(proj_mma_kernel, cudaFuncAttributeMaxDynamicSharedMemorySize, GEMM_SMEM);
        cudaFuncSetAttribute(outproj_mma_kernel, cudaFuncAttributeMaxDynamicSharedMemorySize, GEMM_SMEM);
        cudaFuncSetAttribute(attn_kernel, cudaFuncAttributeMaxDynamicSharedMemorySize, ATTN_SMEM);
        attr_done = true;
    }

    dim3 cgrid(128, 16, 6);
    convert_all<<<cgrid, 256>>>(q, kv, Wq, Wk, Wv, Wo);

    dim3 pgrid(C / 128, (B * NN) / 128, 3);
    proj_mma_kernel<<<pgrid, 256, GEMM_SMEM>>>(pos_q, pos_k);

    dim3 agrid(NN / 256, B * H);
    attn_kernel<<<agrid, 512, ATTN_SMEM>>>();

    dim3 ogrid(C / 128, (B * NN) / 128);
    outproj_mma_kernel<<<ogrid, 256, GEMM_SMEM>>>(bo, out);
}